// round 1
// baseline (speedup 1.0000x reference)
#include <cuda_runtime.h>

#define B_    64
#define Himg  56
#define Wimg  56
#define C_    128
#define N_    3136          // Himg*Wimg
#define NHEAD 4
#define HD    32
#define M_TOT (B_ * N_)     // 200704

// Scratch (allocation-free rule: device globals)
__device__ float g_qkv[(size_t)M_TOT * 384];   // 308 MB
__device__ float g_attn[(size_t)M_TOT * C_];   // 103 MB

// ---------------------------------------------------------------------------
// SGEMM: C[M,N] = A[M,K] @ W[N,K]^T (+ bias[N])
// BM=BN=128, BK=16, 256 threads, 8x8 micro-tile with stride-16 fragments.
// ---------------------------------------------------------------------------
#define BM 128
#define BN 128
#define BK 16

__global__ __launch_bounds__(256) void sgemm_nt(
    const float* __restrict__ A, const float* __restrict__ W,
    float* __restrict__ C, int M, int N, int K,
    const float* __restrict__ bias)
{
    __shared__ float As[BM][BK + 1];
    __shared__ float Ws[BN][BK + 1];

    const int tid = threadIdx.x;
    const int tx = tid & 15;         // column group
    const int ty = tid >> 4;         // row group
    const int m0 = blockIdx.y * BM;
    const int n0 = blockIdx.x * BN;

    float acc[8][8];
#pragma unroll
    for (int i = 0; i < 8; i++)
#pragma unroll
        for (int j = 0; j < 8; j++) acc[i][j] = 0.f;

    for (int kt = 0; kt < K; kt += BK) {
        // Load tiles: natural layout (row r, k). Consecutive tid -> consecutive k.
#pragma unroll
        for (int l = 0; l < (BM * BK) / 256; l++) {
            int e = tid + l * 256;
            int r = e >> 4, k = e & 15;
            As[r][k] = A[(size_t)(m0 + r) * K + kt + k];
        }
#pragma unroll
        for (int l = 0; l < (BN * BK) / 256; l++) {
            int e = tid + l * 256;
            int r = e >> 4, k = e & 15;
            Ws[r][k] = W[(size_t)(n0 + r) * K + kt + k];
        }
        __syncthreads();

#pragma unroll
        for (int kk = 0; kk < BK; kk++) {
            float a[8], w[8];
#pragma unroll
            for (int i = 0; i < 8; i++) a[i] = As[ty + 16 * i][kk];
#pragma unroll
            for (int j = 0; j < 8; j++) w[j] = Ws[tx + 16 * j][kk];
#pragma unroll
            for (int i = 0; i < 8; i++)
#pragma unroll
                for (int j = 0; j < 8; j++) acc[i][j] += a[i] * w[j];
        }
        __syncthreads();
    }

#pragma unroll
    for (int i = 0; i < 8; i++) {
        int row = m0 + ty + 16 * i;
#pragma unroll
        for (int j = 0; j < 8; j++) {
            int col = n0 + tx + 16 * j;
            float v = acc[i][j];
            if (bias) v += bias[col];
            C[(size_t)row * N + col] = v;
        }
    }
}

// ---------------------------------------------------------------------------
// Windowed attention: one block per (batch, window, head). 128 threads.
// q/k/v (49x32) in smem (rows padded to 52 with zeros), scores 52x52.
// ---------------------------------------------------------------------------
__global__ __launch_bounds__(128) void attn_kernel()
{
    const int idx = blockIdx.x;
    const int h = idx & 3;
    const int g = (idx >> 2) & 63;
    const int b = idx >> 8;
    const int gy = g >> 3, gx = g & 7;

    __shared__ float qs[52][33];
    __shared__ float ks[52][33];
    __shared__ float vs[52][33];
    __shared__ float S[52 * 52];

    const int tid = threadIdx.x;

    // Load q, k, v head-slices for this window
    for (int l = tid; l < 49 * 32; l += 128) {
        int i = l >> 5, c = l & 31;
        int n = (gy * 7 + i / 7) * 56 + gx * 7 + (i % 7);
        int base = (b * N_ + n) * 384 + h * 32 + c;
        qs[i][c] = g_qkv[base];
        ks[i][c] = g_qkv[base + 128];
        vs[i][c] = g_qkv[base + 256];
    }
    // Zero the pad rows 49..51
    for (int l = tid; l < 3 * 32; l += 128) {
        int r = 49 + l / 32, c = l & 31;
        qs[r][c] = 0.f; ks[r][c] = 0.f; vs[r][c] = 0.f;
    }
    __syncthreads();

    const float scale = 0.17677669529663687f;   // 32^-0.5

    // S = scale * q @ k^T, 13x13 tiles of 4x4
    for (int t = tid; t < 169; t += 128) {
        int ti = (t / 13) * 4, tj = (t % 13) * 4;
        float acc[4][4];
#pragma unroll
        for (int ii = 0; ii < 4; ii++)
#pragma unroll
            for (int jj = 0; jj < 4; jj++) acc[ii][jj] = 0.f;
#pragma unroll
        for (int c = 0; c < 32; c++) {
            float a[4], bb[4];
#pragma unroll
            for (int ii = 0; ii < 4; ii++) a[ii] = qs[ti + ii][c];
#pragma unroll
            for (int jj = 0; jj < 4; jj++) bb[jj] = ks[tj + jj][c];
#pragma unroll
            for (int ii = 0; ii < 4; ii++)
#pragma unroll
                for (int jj = 0; jj < 4; jj++) acc[ii][jj] += a[ii] * bb[jj];
        }
#pragma unroll
        for (int ii = 0; ii < 4; ii++)
#pragma unroll
            for (int jj = 0; jj < 4; jj++)
                S[(ti + ii) * 52 + tj + jj] = acc[ii][jj] * scale;
    }
    __syncthreads();

    // Softmax: one row per thread (rows 0..48)
    if (tid < 49) {
        float m = -1e30f;
        for (int j = 0; j < 49; j++) m = fmaxf(m, S[tid * 52 + j]);
        float s = 0.f;
        for (int j = 0; j < 49; j++) {
            float e = __expf(S[tid * 52 + j] - m);
            S[tid * 52 + j] = e;
            s += e;
        }
        float inv = __fdividef(1.f, s);
        for (int j = 0; j < 49; j++) S[tid * 52 + j] *= inv;
    }
    __syncthreads();

    // O = P @ v, tiles over (i,d): 13 x 8 = 104 tiles of 4x4
    if (tid < 104) {
        int ti = (tid >> 3) * 4, td = (tid & 7) * 4;
        float acc[4][4];
#pragma unroll
        for (int ii = 0; ii < 4; ii++)
#pragma unroll
            for (int dd = 0; dd < 4; dd++) acc[ii][dd] = 0.f;
        for (int j = 0; j < 49; j++) {
            float p[4], v[4];
#pragma unroll
            for (int ii = 0; ii < 4; ii++) p[ii] = S[(ti + ii) * 52 + j];
#pragma unroll
            for (int dd = 0; dd < 4; dd++) v[dd] = vs[j][td + dd];
#pragma unroll
            for (int ii = 0; ii < 4; ii++)
#pragma unroll
                for (int dd = 0; dd < 4; dd++) acc[ii][dd] += p[ii] * v[dd];
        }
#pragma unroll
        for (int ii = 0; ii < 4; ii++) {
            int i = ti + ii;
            if (i < 49) {
                int n = (gy * 7 + i / 7) * 56 + gx * 7 + (i % 7);
                int ob = (b * N_ + n) * 128 + h * 32 + td;
#pragma unroll
                for (int dd = 0; dd < 4; dd++) g_attn[ob + dd] = acc[ii][dd];
            }
        }
    }
}

// ---------------------------------------------------------------------------
// Depthwise 3x3 conv on V (SAME, zero pad) + bias, added in-place to g_attn.
// One thread per output element.
// ---------------------------------------------------------------------------
__global__ __launch_bounds__(256) void conv_lim(
    const float* __restrict__ w_lim, const float* __restrict__ b_lim)
{
    int idx = blockIdx.x * 256 + threadIdx.x;      // < 25,690,112
    int c = idx & 127;
    int n = (idx >> 7) % N_;
    int b = idx / (N_ * C_);
    int y = n / 56, x = n % 56;

    float s = b_lim[c];
#pragma unroll
    for (int ky = 0; ky < 3; ky++) {
        int yy = y + ky - 1;
        if (yy < 0 || yy >= 56) continue;
#pragma unroll
        for (int kx = 0; kx < 3; kx++) {
            int xx = x + kx - 1;
            if (xx < 0 || xx >= 56) continue;
            s += w_lim[c * 9 + ky * 3 + kx] *
                 g_qkv[(b * N_ + yy * 56 + xx) * 384 + 256 + c];
        }
    }
    g_attn[idx] += s;
}

// ---------------------------------------------------------------------------
extern "C" void kernel_launch(void* const* d_in, const int* in_sizes, int n_in,
                              void* d_out, int out_size)
{
    const float* x      = (const float*)d_in[0];
    const float* w_qkv  = (const float*)d_in[1];
    const float* w_lim  = (const float*)d_in[2];
    const float* b_lim  = (const float*)d_in[3];
    const float* w_proj = (const float*)d_in[4];
    const float* b_proj = (const float*)d_in[5];
    float* out = (float*)d_out;

    float *qkv_ptr, *attn_ptr;
    cudaGetSymbolAddress((void**)&qkv_ptr,  g_qkv);
    cudaGetSymbolAddress((void**)&attn_ptr, g_attn);

    // 1) qkv = x @ w_qkv^T     (M=200704, N=384, K=128)
    {
        dim3 grid(384 / BN, M_TOT / BM);
        sgemm_nt<<<grid, 256>>>(x, w_qkv, qkv_ptr, M_TOT, 384, 128, nullptr);
    }
    // 2) windowed attention -> g_attn
    attn_kernel<<<B_ * 64 * NHEAD, 128>>>();
    // 3) depthwise conv(v) + b_lim, added in place into g_attn
    conv_lim<<<(M_TOT * C_) / 256, 256>>>(w_lim, b_lim);
    // 4) out = g_attn @ w_proj^T + b_proj   (M=200704, N=128, K=128)
    {
        dim3 grid(128 / BN, M_TOT / BM);
        sgemm_nt<<<grid, 256>>>(attn_ptr, w_proj, out, M_TOT, 128, 128, b_proj);
    }
}

// round 3
// speedup vs baseline: 1.4982x; 1.4982x over previous
#include <cuda_runtime.h>
#include <cuda_bf16.h>
#include <cstdint>

#define B_    64
#define Himg  56
#define Wimg  56
#define C_    128
#define N_    3136
#define NHEAD 4
#define M_TOT (B_ * N_)     // 200704

// Scratch (allocation-free rule: device globals)
__device__ float g_qkv[(size_t)M_TOT * 384];           // 308 MB
__device__ float g_attn[(size_t)M_TOT * C_];           // 103 MB
__device__ __nv_bfloat16 g_wh[512 * 128];              // weights hi (qkv rows 0..383, proj 384..511)
__device__ __nv_bfloat16 g_wl[512 * 128];              // weights lo

// ============================================================================
// Weight split prep: fp32 -> bf16 hi/lo
// ============================================================================
__global__ void prep_weights(const float* __restrict__ w_qkv,
                             const float* __restrict__ w_proj)
{
    int idx = blockIdx.x * 256 + threadIdx.x;
    if (idx >= 512 * 128) return;
    float w = (idx < 384 * 128) ? w_qkv[idx] : w_proj[idx - 384 * 128];
    __nv_bfloat16 hi = __float2bfloat16(w);
    float r = w - __bfloat162float(hi);
    g_wh[idx] = hi;
    g_wl[idx] = __float2bfloat16(r);
}

// ============================================================================
// HMMA GEMM: C[M, ldc] = A[M,128] @ W[N,128]^T (+bias), 3-term bf16 split.
// Tile 128x128, 256 threads (8 warps, 4x2), warp tile 32x64.
// mma.sync.aligned.m16n8k16.row.col.f32.bf16.bf16.f32
// ============================================================================
#define LDT 136                      // padded row stride in bf16 elements (272 B)
#define TILE_B (128 * LDT * 2)       // 34816 B per tile
#define SM_AHI 0
#define SM_ALO (TILE_B)
#define SM_WHI (2 * TILE_B)
#define SM_WLO (3 * TILE_B)
#define SM_BYTES (4 * TILE_B)

__device__ __forceinline__ uint32_t smem_u32(const void* p) {
    uint32_t a;
    asm("{ .reg .u64 t; cvta.to.shared.u64 t, %1; cvt.u32.u64 %0, t; }" : "=r"(a) : "l"(p));
    return a;
}

__device__ __forceinline__ uint32_t pack2(float a, float b) {
    __nv_bfloat16 ha = __float2bfloat16(a), hb = __float2bfloat16(b);
    unsigned short ua = reinterpret_cast<unsigned short&>(ha);
    unsigned short ub = reinterpret_cast<unsigned short&>(hb);
    return (uint32_t)ua | ((uint32_t)ub << 16);
}

__device__ __forceinline__ void mma16816(float* d, const uint32_t* a, const uint32_t* b) {
    asm volatile(
        "mma.sync.aligned.m16n8k16.row.col.f32.bf16.bf16.f32 "
        "{%0,%1,%2,%3}, {%4,%5,%6,%7}, {%8,%9}, {%0,%1,%2,%3};"
        : "+f"(d[0]), "+f"(d[1]), "+f"(d[2]), "+f"(d[3])
        : "r"(a[0]), "r"(a[1]), "r"(a[2]), "r"(a[3]), "r"(b[0]), "r"(b[1]));
}

__global__ void __launch_bounds__(256)
hmma_gemm(const float* __restrict__ A,
          const __nv_bfloat16* __restrict__ whi,
          const __nv_bfloat16* __restrict__ wlo,
          float* __restrict__ C, int ldc,
          const float* __restrict__ bias)
{
    extern __shared__ char smem[];
    const uint32_t sb = smem_u32(smem);
    const int tid = threadIdx.x;
    const int wid = tid >> 5;
    const int lane = tid & 31;
    const int m0 = blockIdx.y * 128;
    const int n0 = blockIdx.x * 128;

    // ---- Load + split A tile (128 x 128 fp32 -> bf16 hi/lo) ----
#pragma unroll
    for (int it = 0; it < 8; it++) {
        int e = it * 256 + tid;          // 2048 chunks of 8 k-cols
        int r = e >> 4;
        int k0 = (e & 15) * 8;
        const float4* p = reinterpret_cast<const float4*>(A + (size_t)(m0 + r) * 128 + k0);
        float4 x0 = p[0], x1 = p[1];
        float f[8] = {x0.x, x0.y, x0.z, x0.w, x1.x, x1.y, x1.z, x1.w};
        uint32_t h[4], l[4];
#pragma unroll
        for (int j = 0; j < 4; j++) {
            float a = f[2 * j], b = f[2 * j + 1];
            __nv_bfloat16 ha = __float2bfloat16(a), hb = __float2bfloat16(b);
            float ra = a - __bfloat162float(ha);
            float rb = b - __bfloat162float(hb);
            unsigned short ua = reinterpret_cast<unsigned short&>(ha);
            unsigned short ub = reinterpret_cast<unsigned short&>(hb);
            h[j] = (uint32_t)ua | ((uint32_t)ub << 16);
            l[j] = pack2(ra, rb);
        }
        uint32_t off = (uint32_t)(r * LDT + k0) * 2;
        *reinterpret_cast<uint4*>(smem + SM_AHI + off) = make_uint4(h[0], h[1], h[2], h[3]);
        *reinterpret_cast<uint4*>(smem + SM_ALO + off) = make_uint4(l[0], l[1], l[2], l[3]);
    }
    // ---- Load W tiles (already bf16) ----
#pragma unroll
    for (int it = 0; it < 8; it++) {
        int e = it * 256 + tid;
        int r = e >> 4;
        int k0 = (e & 15) * 8;
        uint32_t off = (uint32_t)(r * LDT + k0) * 2;
        *reinterpret_cast<uint4*>(smem + SM_WHI + off) =
            *reinterpret_cast<const uint4*>(whi + (size_t)(n0 + r) * 128 + k0);
        *reinterpret_cast<uint4*>(smem + SM_WLO + off) =
            *reinterpret_cast<const uint4*>(wlo + (size_t)(n0 + r) * 128 + k0);
    }
    __syncthreads();

    // ---- Warp tiling: 4 warps along M, 2 along N ----
    const int mrow = (wid & 3) * 32;       // warp base row in tile
    const int ncol = (wid >> 2) * 64;      // warp base col in tile
    const int grp = lane >> 2;             // 0..7
    const int thr4 = lane & 3;             // 0..3

    float acc[2][8][4];
#pragma unroll
    for (int mt = 0; mt < 2; mt++)
#pragma unroll
        for (int nt = 0; nt < 8; nt++)
#pragma unroll
            for (int j = 0; j < 4; j++) acc[mt][nt][j] = 0.f;

#pragma unroll
    for (int pass = 0; pass < 3; pass++) {
        const uint32_t sA = sb + ((pass == 2) ? SM_ALO : SM_AHI);
        const uint32_t sB = sb + ((pass == 1) ? SM_WLO : SM_WHI);
#pragma unroll
        for (int ks = 0; ks < 8; ks++) {
            const int k0 = ks * 16;
            uint32_t afr[2][4];
#pragma unroll
            for (int mt = 0; mt < 2; mt++) {
                int r = mrow + mt * 16 + grp;
                uint32_t base = sA + (uint32_t)(r * LDT + k0 + thr4 * 2) * 2;
                asm volatile("ld.shared.b32 %0, [%1];" : "=r"(afr[mt][0]) : "r"(base));
                asm volatile("ld.shared.b32 %0, [%1];" : "=r"(afr[mt][1]) : "r"(base + 8 * LDT * 2));
                asm volatile("ld.shared.b32 %0, [%1];" : "=r"(afr[mt][2]) : "r"(base + 16));
                asm volatile("ld.shared.b32 %0, [%1];" : "=r"(afr[mt][3]) : "r"(base + 8 * LDT * 2 + 16));
            }
#pragma unroll
            for (int nt = 0; nt < 8; nt++) {
                int n = ncol + nt * 8 + grp;
                uint32_t base = sB + (uint32_t)(n * LDT + k0 + thr4 * 2) * 2;
                uint32_t bfr[2];
                asm volatile("ld.shared.b32 %0, [%1];" : "=r"(bfr[0]) : "r"(base));
                asm volatile("ld.shared.b32 %0, [%1];" : "=r"(bfr[1]) : "r"(base + 16));
#pragma unroll
                for (int mt = 0; mt < 2; mt++)
                    mma16816(acc[mt][nt], afr[mt], bfr);
            }
        }
    }

    // ---- Epilogue ----
#pragma unroll
    for (int mt = 0; mt < 2; mt++) {
        int r0 = m0 + mrow + mt * 16 + grp;
#pragma unroll
        for (int nt = 0; nt < 8; nt++) {
            int c = n0 + ncol + nt * 8 + thr4 * 2;
            float bx = 0.f, by = 0.f;
            if (bias) { bx = bias[c]; by = bias[c + 1]; }
            float2 v0 = make_float2(acc[mt][nt][0] + bx, acc[mt][nt][1] + by);
            float2 v1 = make_float2(acc[mt][nt][2] + bx, acc[mt][nt][3] + by);
            *reinterpret_cast<float2*>(C + (size_t)r0 * ldc + c) = v0;
            *reinterpret_cast<float2*>(C + (size_t)(r0 + 8) * ldc + c) = v1;
        }
    }
}

// ============================================================================
// Windowed attention: one block per (batch, window, head). 224 threads.
// ============================================================================
__global__ __launch_bounds__(224) void attn_kernel()
{
    const int idx = blockIdx.x;
    const int h = idx & 3;
    const int g = (idx >> 2) & 63;
    const int b = idx >> 8;
    const int gy = g >> 3, gx = g & 7;

    __shared__ float qs[52][33];
    __shared__ float ks[52][33];
    __shared__ float vs[52][33];
    __shared__ float S[52 * 52];

    const int tid = threadIdx.x;

    for (int l = tid; l < 49 * 32; l += 224) {
        int i = l >> 5, c = l & 31;
        int n = (gy * 7 + i / 7) * 56 + gx * 7 + (i % 7);
        int base = (b * N_ + n) * 384 + h * 32 + c;
        qs[i][c] = g_qkv[base];
        ks[i][c] = g_qkv[base + 128];
        vs[i][c] = g_qkv[base + 256];
    }
    if (tid < 96) {
        int r = 49 + tid / 32, c = tid & 31;
        qs[r][c] = 0.f; ks[r][c] = 0.f; vs[r][c] = 0.f;
    }
    __syncthreads();

    const float scale = 0.17677669529663687f;   // 32^-0.5

    if (tid < 169) {
        int ti = (tid / 13) * 4, tj = (tid % 13) * 4;
        float acc[4][4];
#pragma unroll
        for (int ii = 0; ii < 4; ii++)
#pragma unroll
            for (int jj = 0; jj < 4; jj++) acc[ii][jj] = 0.f;
#pragma unroll
        for (int c = 0; c < 32; c++) {
            float a[4], bb[4];
#pragma unroll
            for (int ii = 0; ii < 4; ii++) a[ii] = qs[ti + ii][c];
#pragma unroll
            for (int jj = 0; jj < 4; jj++) bb[jj] = ks[tj + jj][c];
#pragma unroll
            for (int ii = 0; ii < 4; ii++)
#pragma unroll
                for (int jj = 0; jj < 4; jj++) acc[ii][jj] += a[ii] * bb[jj];
        }
#pragma unroll
        for (int ii = 0; ii < 4; ii++)
#pragma unroll
            for (int jj = 0; jj < 4; jj++)
                S[(ti + ii) * 52 + tj + jj] = acc[ii][jj] * scale;
    }
    __syncthreads();

    if (tid < 49) {
        float m = -1e30f;
        for (int j = 0; j < 49; j++) m = fmaxf(m, S[tid * 52 + j]);
        float s = 0.f;
        for (int j = 0; j < 49; j++) {
            float e = __expf(S[tid * 52 + j] - m);
            S[tid * 52 + j] = e;
            s += e;
        }
        float inv = __fdividef(1.f, s);
        for (int j = 0; j < 49; j++) S[tid * 52 + j] *= inv;
    }
    __syncthreads();

    if (tid < 104) {
        int ti = (tid >> 3) * 4, td = (tid & 7) * 4;
        float acc[4][4];
#pragma unroll
        for (int ii = 0; ii < 4; ii++)
#pragma unroll
            for (int dd = 0; dd < 4; dd++) acc[ii][dd] = 0.f;
        for (int j = 0; j < 49; j++) {
            float p[4], v[4];
#pragma unroll
            for (int ii = 0; ii < 4; ii++) p[ii] = S[(ti + ii) * 52 + j];
#pragma unroll
            for (int dd = 0; dd < 4; dd++) v[dd] = vs[j][td + dd];
#pragma unroll
            for (int ii = 0; ii < 4; ii++)
#pragma unroll
                for (int dd = 0; dd < 4; dd++) acc[ii][dd] += p[ii] * v[dd];
        }
#pragma unroll
        for (int ii = 0; ii < 4; ii++) {
            int i = ti + ii;
            if (i < 49) {
                int n = (gy * 7 + i / 7) * 56 + gx * 7 + (i % 7);
                int ob = (b * N_ + n) * 128 + h * 32 + td;
#pragma unroll
                for (int dd = 0; dd < 4; dd++) g_attn[ob + dd] = acc[ii][dd];
            }
        }
    }
}

// ============================================================================
// Depthwise 3x3 conv on V + bias, added in-place to g_attn.
// ============================================================================
__global__ __launch_bounds__(256) void conv_lim(
    const float* __restrict__ w_lim, const float* __restrict__ b_lim)
{
    int idx = blockIdx.x * 256 + threadIdx.x;
    int c = idx & 127;
    int n = (idx >> 7) % N_;
    int b = idx / (N_ * C_);
    int y = n / 56, x = n % 56;

    float s = b_lim[c];
#pragma unroll
    for (int ky = 0; ky < 3; ky++) {
        int yy = y + ky - 1;
        if (yy < 0 || yy >= 56) continue;
#pragma unroll
        for (int kx = 0; kx < 3; kx++) {
            int xx = x + kx - 1;
            if (xx < 0 || xx >= 56) continue;
            s += w_lim[c * 9 + ky * 3 + kx] *
                 g_qkv[(size_t)(b * N_ + yy * 56 + xx) * 384 + 256 + c];
        }
    }
    g_attn[idx] += s;
}

// ============================================================================
extern "C" void kernel_launch(void* const* d_in, const int* in_sizes, int n_in,
                              void* d_out, int out_size)
{
    const float* x      = (const float*)d_in[0];
    const float* w_qkv  = (const float*)d_in[1];
    const float* w_lim  = (const float*)d_in[2];
    const float* b_lim  = (const float*)d_in[3];
    const float* w_proj = (const float*)d_in[4];
    const float* b_proj = (const float*)d_in[5];
    float* out = (float*)d_out;

    float *qkv_ptr, *attn_ptr;
    __nv_bfloat16 *wh_ptr, *wl_ptr;
    cudaGetSymbolAddress((void**)&qkv_ptr,  g_qkv);
    cudaGetSymbolAddress((void**)&attn_ptr, g_attn);
    cudaGetSymbolAddress((void**)&wh_ptr,   g_wh);
    cudaGetSymbolAddress((void**)&wl_ptr,   g_wl);

    cudaFuncSetAttribute(hmma_gemm, cudaFuncAttributeMaxDynamicSharedMemorySize, SM_BYTES);

    // 0) split weights into bf16 hi/lo
    prep_weights<<<(512 * 128 + 255) / 256, 256>>>(w_qkv, w_proj);

    // 1) qkv = x @ w_qkv^T   (HMMA bf16 3-term split)
    hmma_gemm<<<dim3(3, M_TOT / 128), 256, SM_BYTES>>>(x, wh_ptr, wl_ptr, qkv_ptr, 384, nullptr);

    // 2) windowed attention
    attn_kernel<<<B_ * 64 * NHEAD, 224>>>();

    // 3) depthwise conv(v) + b_lim into g_attn
    conv_lim<<<(M_TOT * C_) / 256, 256>>>(w_lim, b_lim);

    // 4) out = g_attn @ w_proj^T + b_proj
    hmma_gemm<<<dim3(1, M_TOT / 128), 256, SM_BYTES>>>(attn_ptr, wh_ptr + 384 * 128,
                                                       wl_ptr + 384 * 128, out, 128, b_proj);
}